// round 16
// baseline (speedup 1.0000x reference)
#include <cuda_runtime.h>
#include <cstdint>

// ============================================================================
// OneHotEncoding — single kernel, zero grid barriers, block-local argmin.
//
// R15 base (best: 30.8us; sphere-exact build, 8pt/thread barrier-free stream).
// R16 change: the per-block-redundant UB probe was the largest instruction
// consumer (~4.8M warp-instrs, 20M scalar pair-evals). Now:
//   - packed f32x2 math (2 points per fma-pipe issue, points loaded pairwise
//     via a single LDS.64 from the SoA arrays — zero packing cost)
//   - PROBE_N 1024 -> 512 (UB grows ~0.055 -> ~0.08; KCAP 5 -> 6 absorbs it)
// Probe cost ~4.8M -> ~1.5M warp-instrs. Everything else byte-identical.
//
// Output layout (float32):
//   [0, 4L)            input_tensor: per point (x, y, z, one_hot)
//   [4L, 4L+3B)        closest_points [B,3]
//   [4L+3B, 4L+4B)     min_index as float [B]
//
// Merge key: ~((u64)d2bits<<32 | idx), combined with max.
//   - zero-initialized .bss g_best IS the identity (no init pass)
//   - max of complement == min (d2, idx) => first-index tie-break
//   - probe seed ~(probe_d2<<32 | 0xFFFFFFFF) is provably below the true
//     winner's key: filters only, never decides.
//   - finalize resets g_best/g_done to 0 => graph-replay deterministic.
//
// Candidate table: cell admitted for receiver r iff min-dist(r, cell)^2 <=
// guarded UB^2 (UB = exact distance to a real sampled point). The true NN's
// cell always qualifies. Cells with >KCAP receivers get sentinel 255 =>
// brute-force all B there. Unconditionally correct.
// ============================================================================

#define GC       16
#define CELLS    (GC * GC * GC)        // 4096
#define MAXB     128
#define GRID     152
#define THREADS  1024
#define KCAP     6                     // candidate list slots per cell
#define PROBE_N  512                   // sample points for UB probe

__device__ unsigned long long g_best[MAXB];   // complemented keys; 0 = identity
__device__ unsigned int       g_done;         // zero-init; self-resetting

// ---- Blackwell packed f32x2 helpers (2 fp32 ops per fma-pipe issue) ----
#define ADD2(o,a,b)   asm("add.rn.f32x2 %0, %1, %2;"     : "=l"(o) : "l"(a), "l"(b))
#define MUL2(o,a,b)   asm("mul.rn.f32x2 %0, %1, %2;"     : "=l"(o) : "l"(a), "l"(b))
#define FMA2(o,a,b,c) asm("fma.rn.f32x2 %0, %1, %2, %3;" : "=l"(o) : "l"(a), "l"(b), "l"(c))
#define PACK2(o,lo,hi)  asm("mov.b64 %0, {%1, %2};" : "=l"(o) : "r"(lo), "r"(hi))
#define UNPACK2(lo,hi,i) asm("mov.b64 {%0, %1}, %2;" : "=r"(lo), "=r"(hi) : "l"(i))

// full-clamp version (probe/build: r-UB may leave [0,1))
__device__ __forceinline__ int cell_of(float x) {
    int c = __float2int_rd(x * (float)GC);
    c = c < 0 ? 0 : c;
    return c > GC - 1 ? GC - 1 : c;
}
// stream version: data coords are in [0,1) => only upper guard needed
__device__ __forceinline__ int cell_fast(float x) {
    return (int)fminf(x * (float)GC, (float)(GC - 1));
}

// ---------------------------------------------------------------------------
__global__ void __launch_bounds__(THREADS, 1)
fused_kernel(const float* __restrict__ pts, const float* __restrict__ recv,
             float* __restrict__ out, int L, int B)
{
    const int tid  = threadIdx.x;
    const int lane = tid & 31;
    const int wid  = tid >> 5;
    const int bid  = blockIdx.x;

    __shared__ float srx[MAXB], sry[MAXB], srz[MAXB];
    __shared__ float s_ub[MAXB];                       // probe min d2 per recv
    __shared__ unsigned long long s_best[MAXB];        // block-local keys
    __shared__ unsigned char s_list[CELLS * KCAP];     // 24 KB
    __shared__ unsigned char s_cnt[CELLS];             // 4 KB (255 = overflow)
    // scratch: probe SoA (6 KB) then cnt32 (16 KB)
    __shared__ __align__(16) unsigned char s_scratch[16384];

    // ---- stage receivers ----
    if (tid < B) {
        srx[tid] = recv[3 * tid + 0];
        sry[tid] = recv[3 * tid + 1];
        srz[tid] = recv[3 * tid + 2];
    }

    // ---- stage probe samples SoA into scratch ----
    float* s_px = reinterpret_cast<float*>(s_scratch);
    float* s_py = s_px + PROBE_N;
    float* s_pz = s_py + PROBE_N;
    const int n  = (L < PROBE_N) ? L : PROBE_N;
    const int n3 = n * 3;
#pragma unroll
    for (int j = 0; j < 2; ++j) {
        int e = tid + j * THREADS;                 // [0, 2048)
        if (e < PROBE_N * 3) {
            float v = (e < n3) ? pts[e] : 1.0e30f;
            int p = e / 3, c = e - p * 3;
            if      (c == 0) s_px[p] = v;
            else if (c == 1) s_py[p] = v;
            else             s_pz[p] = v;
        }
    }
    __syncthreads();

    // ---- UB probe (packed f32x2): warp wid owns receivers [4*wid, 4*wid+4) ----
    {
        const int rbase = wid * 4;
        unsigned long long nrx[4], nry[4], nrz[4];
        float bd[4];
#pragma unroll
        for (int k = 0; k < 4; ++k) {
            int rb = rbase + k;
            float x = (rb < B) ? -srx[rb] : 0.f;
            float y = (rb < B) ? -sry[rb] : 0.f;
            float z = (rb < B) ? -srz[rb] : 0.f;
            unsigned int xu = __float_as_uint(x);
            unsigned int yu = __float_as_uint(y);
            unsigned int zu = __float_as_uint(z);
            PACK2(nrx[k], xu, xu);
            PACK2(nry[k], yu, yu);
            PACK2(nrz[k], zu, zu);
            bd[k] = 3.4e38f;
        }
#pragma unroll 2
        for (int j = 0; j < PROBE_N / 64; ++j) {   // 2 points/lane/iter
            int i = 2 * lane + 64 * j;             // even => 8B-aligned LDS.64
            unsigned long long Px = *reinterpret_cast<unsigned long long*>(&s_px[i]);
            unsigned long long Py = *reinterpret_cast<unsigned long long*>(&s_py[i]);
            unsigned long long Pz = *reinterpret_cast<unsigned long long*>(&s_pz[i]);
#pragma unroll
            for (int k = 0; k < 4; ++k) {
                unsigned long long dx, dy, dz, s;
                ADD2(dx, Px, nrx[k]);              // p - r (exact sub)
                ADD2(dy, Py, nry[k]);
                ADD2(dz, Pz, nrz[k]);
                MUL2(s, dx, dx);
                FMA2(s, dy, dy, s);
                FMA2(s, dz, dz, s);
                unsigned int u0, u1;
                UNPACK2(u0, u1, s);
                bd[k] = fminf(bd[k],
                              fminf(__uint_as_float(u0), __uint_as_float(u1)));
            }
        }
#pragma unroll
        for (int k = 0; k < 4; ++k) {
#pragma unroll
            for (int m = 16; m > 0; m >>= 1)
                bd[k] = fminf(bd[k], __shfl_xor_sync(0xffffffffu, bd[k], m));
            if (lane == 0 && (rbase + k) < B) {
                s_ub[rbase + k] = bd[k];
                // seed: <= true winner's key (d2 >= true d2, idx field maximal)
                s_best[rbase + k] =
                    ~((((unsigned long long)__float_as_uint(bd[k])) << 32) |
                      0xFFFFFFFFull);
            }
        }
    }
    __syncthreads();

    // ---- zero cnt32 (reuses scratch) ----
    unsigned int* cnt32 = reinterpret_cast<unsigned int*>(s_scratch);
#pragma unroll
    for (int j = 0; j < CELLS / THREADS; ++j) cnt32[tid + j * THREADS] = 0u;
    __syncthreads();

    // ---- build candidate lists (receiver-major, sphere-exact filter) ----
    if (tid < B) {
        float ub  = sqrtf(s_ub[tid]) * 1.0001f + 1e-7f;  // ulp guard
        float ub2 = ub * ub;
        const float h = 1.0f / (float)GC;
        float rx = srx[tid], ry = sry[tid], rz = srz[tid];
        int lx = cell_of(rx - ub), hx = cell_of(rx + ub);
        int ly = cell_of(ry - ub), hy = cell_of(ry + ub);
        int lz = cell_of(rz - ub), hz = cell_of(rz + ub);
        for (int zz = lz; zz <= hz; ++zz) {
            float dz = fmaxf(fmaxf((float)zz * h - rz, rz - (float)(zz + 1) * h), 0.f);
            for (int yy = ly; yy <= hy; ++yy) {
                float dy = fmaxf(fmaxf((float)yy * h - ry, ry - (float)(yy + 1) * h), 0.f);
                float dzy = dz * dz + dy * dy;
                for (int xx = lx; xx <= hx; ++xx) {
                    float dx = fmaxf(fmaxf((float)xx * h - rx, rx - (float)(xx + 1) * h), 0.f);
                    if (dzy + dx * dx <= ub2) {          // sphere-exact test
                        int c = (zz * GC + yy) * GC + xx;
                        unsigned int pos = atomicAdd(&cnt32[c], 1u);
                        if (pos < KCAP) s_list[c * KCAP + pos] = (unsigned char)tid;
                    }
                }
            }
        }
    }
    __syncthreads();

    // ---- compact counts to u8 with overflow sentinel ----
#pragma unroll
    for (int j = 0; j < CELLS / THREADS; ++j) {
        int c = tid + j * THREADS;
        unsigned int v = cnt32[c];
        s_cnt[c] = (v > KCAP) ? (unsigned char)255 : (unsigned char)v;
    }
    __syncthreads();

    // ---- streaming pass: BARRIER-FREE, 8 pts/thread, one pass/thread ----
    {
        const int nGrp   = (L + 7) >> 3;                 // 125000 for L=1e6
        const int stride = GRID * THREADS;

        for (int g = bid * THREADS + tid; g < nGrp; g += stride) {
            const int p0 = 8 * g;
            float x[8], y[8], z[8];
            if (p0 + 8 <= L) {                           // fast path: 6x LDG.128
                const float4* src = reinterpret_cast<const float4*>(pts + 3 * p0);
                float4 v0 = src[0], v1 = src[1], v2 = src[2],
                       v3 = src[3], v4 = src[4], v5 = src[5];
                x[0]=v0.x; y[0]=v0.y; z[0]=v0.z;
                x[1]=v0.w; y[1]=v1.x; z[1]=v1.y;
                x[2]=v1.z; y[2]=v1.w; z[2]=v2.x;
                x[3]=v2.y; y[3]=v2.z; z[3]=v2.w;
                x[4]=v3.x; y[4]=v3.y; z[4]=v3.z;
                x[5]=v3.w; y[5]=v4.x; z[5]=v4.y;
                x[6]=v4.z; y[6]=v4.w; z[6]=v5.x;
                x[7]=v5.y; y[7]=v5.z; z[7]=v5.w;
            } else {
#pragma unroll
                for (int j = 0; j < 8; ++j) {
                    int p = p0 + j;
                    x[j] = (p < L) ? pts[3 * p + 0] : 0.5f;  // pad (guarded below)
                    y[j] = (p < L) ? pts[3 * p + 1] : 0.5f;
                    z[j] = (p < L) ? pts[3 * p + 2] : 0.5f;
                }
            }

            float4* obase = reinterpret_cast<float4*>(out) + p0;
#pragma unroll
            for (int j = 0; j < 8; ++j) {
                const int p = p0 + j;
                if (p >= L) break;
                obase[j] = make_float4(x[j], y[j], z[j], 0.0f);

                int c = (cell_fast(z[j]) * GC + cell_fast(y[j])) * GC
                        + cell_fast(x[j]);
                unsigned int cn = s_cnt[c];              // LDS
                if (cn) {
                    int  lim = (cn == 255u) ? B : (int)cn;
                    bool all = (cn == 255u);
                    for (int k = 0; k < lim; ++k) {
                        int r = all ? k : (int)s_list[c * KCAP + k];
                        float dx = x[j] - srx[r];
                        float dy = y[j] - sry[r];
                        float dz = z[j] - srz[r];
                        float d2 = dx * dx + dy * dy + dz * dz;
                        unsigned long long key =
                            ~((((unsigned long long)__float_as_uint(d2)) << 32) |
                              (unsigned long long)(unsigned int)p);
                        // LDS guard block-coherent; smem atomic authoritative
                        if (key > s_best[r]) atomicMax(&s_best[r], key);
                    }
                }
            }
        }
    }
    __syncthreads();   // all smem atomics visible

    // ---- one global merge per block (<=128 atomics) ----
    if (tid < B) atomicMax(&g_best[tid], s_best[tid]);

    // ---- last-finishing block finalizes ----
    __threadfence();
    __syncthreads();
    __shared__ bool is_last;
    if (tid == 0) is_last = (atomicAdd(&g_done, 1u) == GRID - 1);
    __syncthreads();
    if (!is_last) return;

    if (tid < B) {
        // authoritative read (atomicMax with identity 0 leaves value intact)
        unsigned long long key = atomicMax(&g_best[tid], 0ull);
        unsigned int idx = ~((unsigned int)(key & 0xffffffffull));
        float* cp = out + 4 * (size_t)L;
        cp[3 * tid + 0] = pts[3 * idx + 0];
        cp[3 * tid + 1] = pts[3 * idx + 1];
        cp[3 * tid + 2] = pts[3 * idx + 2];
        out[4 * (size_t)L + 3 * B + tid] = (float)idx;   // min_index as float
        out[4 * (size_t)idx + 3] = 1.0f;                 // one-hot scatter
        g_best[tid] = 0ull;                              // reset for next replay
    }
    if (tid == 0) {
        if (B > 1) out[3] = 1.0f;        // reference quirk: index 0 also set
        g_done = 0u;                     // reset for next replay
    }
}

// ---------------------------------------------------------------------------
extern "C" void kernel_launch(void* const* d_in, const int* in_sizes, int n_in,
                              void* d_out, int out_size)
{
    const float* pts  = (const float*)d_in[0];   // mesh_3D flattened [L,3]
    const float* recv = (const float*)d_in[1];   // receiver_pos [B,3]
    float* out = (float*)d_out;

    int L = in_sizes[0] / 3;   // 1,000,000
    int B = in_sizes[1] / 3;   // 128

    fused_kernel<<<GRID, THREADS>>>(pts, recv, out, L, B);
}

// round 17
// speedup vs baseline: 1.3029x; 1.3029x over previous
#include <cuda_runtime.h>
#include <cstdint>

// ============================================================================
// OneHotEncoding — single kernel, zero grid barriers, block-local argmin,
// NO PROBE (R16 lesson: the per-block UB probe was ~10us of stall-exposed
// work; packed-math "optimizing" it regressed). Fixed candidate radius
// R0=0.025 with a provable safety net:
//   - lists cover every cell with min-dist(r, cell) <= R0 (sphere-exact,
//     inflated test R0^2*1.00001 vs seed's exact R0^2);
//   - seed key ~(R0^2<<32 | 0xFFFFFFFF): any RECORDED point has d2 < R0^2,
//     which implies the true NN (d <= recorded d <= R0) had its cell covered
//     and was evaluated => recorded argmin IS the global argmin;
//   - if NOTHING recorded (idx sentinel 0xFFFFFFFF; P ~ 1.5e-4, worst-case
//     corner receivers), the last block BRUTE-FORCES that receiver over all
//     L points. Unconditionally correct; fallback never runs in practice.
//
// Output layout (float32):
//   [0, 4L)            input_tensor: per point (x, y, z, one_hot)
//   [4L, 4L+3B)        closest_points [B,3]
//   [4L+3B, 4L+4B)     min_index as float [B]
//
// Merge key: ~((u64)d2bits<<32 | idx), combined with max.
//   - zero-initialized .bss g_best IS the identity (no init pass)
//   - max of complement == min (d2, idx) => first-index tie-break
//   - finalize resets g_best/g_done to 0 => graph-replay deterministic.
// ============================================================================

#define GC       16
#define CELLS    (GC * GC * GC)        // 4096
#define MAXB     128
#define GRID     152
#define THREADS  1024
#define KCAP     5                     // candidate list slots per cell
#define R0       0.025f                // fixed candidate radius

__device__ unsigned long long g_best[MAXB];   // complemented keys; 0 = identity
__device__ unsigned int       g_done;         // zero-init; self-resetting

// full-clamp version (build: r-R0 may leave [0,1))
__device__ __forceinline__ int cell_of(float x) {
    int c = __float2int_rd(x * (float)GC);
    c = c < 0 ? 0 : c;
    return c > GC - 1 ? GC - 1 : c;
}
// stream version: data coords are in [0,1) => only upper guard needed
__device__ __forceinline__ int cell_fast(float x) {
    return (int)fminf(x * (float)GC, (float)(GC - 1));
}

// ---------------------------------------------------------------------------
__global__ void __launch_bounds__(THREADS, 1)
fused_kernel(const float* __restrict__ pts, const float* __restrict__ recv,
             float* __restrict__ out, int L, int B)
{
    const int tid  = threadIdx.x;
    const int lane = tid & 31;
    const int wid  = tid >> 5;
    const int bid  = blockIdx.x;

    __shared__ float srx[MAXB], sry[MAXB], srz[MAXB];
    __shared__ unsigned long long s_best[MAXB];        // block-local keys
    __shared__ unsigned long long s_red[THREADS / 32]; // fallback reduction
    __shared__ unsigned char s_list[CELLS * KCAP];     // 20 KB
    __shared__ unsigned char s_cnt[CELLS];             // 4 KB (255 = overflow)
    __shared__ unsigned int  cnt32[CELLS];             // 16 KB build counters

    const float ub2_seed = R0 * R0;                    // exact seed threshold
    const float ub2_test = ub2_seed * 1.00001f;        // inflated (fp guard)
    const float r0_box   = R0 * 1.0001f;               // inflated box bound

    // ---- stage receivers + seed block-local bests ----
    if (tid < B) {
        srx[tid] = recv[3 * tid + 0];
        sry[tid] = recv[3 * tid + 1];
        srz[tid] = recv[3 * tid + 2];
        s_best[tid] =
            ~((((unsigned long long)__float_as_uint(ub2_seed)) << 32) |
              0xFFFFFFFFull);          // idx sentinel: triggers fallback
    }

    // ---- zero build counters ----
#pragma unroll
    for (int j = 0; j < CELLS / THREADS; ++j) cnt32[tid + j * THREADS] = 0u;
    __syncthreads();

    // ---- build candidate lists (receiver-major, sphere-exact filter) ----
    if (tid < B) {
        const float h = 1.0f / (float)GC;
        float rx = srx[tid], ry = sry[tid], rz = srz[tid];
        int lx = cell_of(rx - r0_box), hx = cell_of(rx + r0_box);
        int ly = cell_of(ry - r0_box), hy = cell_of(ry + r0_box);
        int lz = cell_of(rz - r0_box), hz = cell_of(rz + r0_box);
        for (int zz = lz; zz <= hz; ++zz) {
            float dz = fmaxf(fmaxf((float)zz * h - rz, rz - (float)(zz + 1) * h), 0.f);
            for (int yy = ly; yy <= hy; ++yy) {
                float dy = fmaxf(fmaxf((float)yy * h - ry, ry - (float)(yy + 1) * h), 0.f);
                float dzy = dz * dz + dy * dy;
                for (int xx = lx; xx <= hx; ++xx) {
                    float dx = fmaxf(fmaxf((float)xx * h - rx, rx - (float)(xx + 1) * h), 0.f);
                    if (dzy + dx * dx <= ub2_test) {     // sphere-exact test
                        int c = (zz * GC + yy) * GC + xx;
                        unsigned int pos = atomicAdd(&cnt32[c], 1u);
                        if (pos < KCAP) s_list[c * KCAP + pos] = (unsigned char)tid;
                    }
                }
            }
        }
    }
    __syncthreads();

    // ---- compact counts to u8 with overflow sentinel ----
#pragma unroll
    for (int j = 0; j < CELLS / THREADS; ++j) {
        int c = tid + j * THREADS;
        unsigned int v = cnt32[c];
        s_cnt[c] = (v > KCAP) ? (unsigned char)255 : (unsigned char)v;
    }
    __syncthreads();

    // ---- streaming pass: BARRIER-FREE, 8 pts/thread, one pass/thread ----
    {
        const int nGrp   = (L + 7) >> 3;                 // 125000 for L=1e6
        const int stride = GRID * THREADS;

        for (int g = bid * THREADS + tid; g < nGrp; g += stride) {
            const int p0 = 8 * g;
            float x[8], y[8], z[8];
            if (p0 + 8 <= L) {                           // fast path: 6x LDG.128
                const float4* src = reinterpret_cast<const float4*>(pts + 3 * p0);
                float4 v0 = src[0], v1 = src[1], v2 = src[2],
                       v3 = src[3], v4 = src[4], v5 = src[5];
                x[0]=v0.x; y[0]=v0.y; z[0]=v0.z;
                x[1]=v0.w; y[1]=v1.x; z[1]=v1.y;
                x[2]=v1.z; y[2]=v1.w; z[2]=v2.x;
                x[3]=v2.y; y[3]=v2.z; z[3]=v2.w;
                x[4]=v3.x; y[4]=v3.y; z[4]=v3.z;
                x[5]=v3.w; y[5]=v4.x; z[5]=v4.y;
                x[6]=v4.z; y[6]=v4.w; z[6]=v5.x;
                x[7]=v5.y; y[7]=v5.z; z[7]=v5.w;
            } else {
#pragma unroll
                for (int j = 0; j < 8; ++j) {
                    int p = p0 + j;
                    x[j] = (p < L) ? pts[3 * p + 0] : 0.5f;  // pad (guarded below)
                    y[j] = (p < L) ? pts[3 * p + 1] : 0.5f;
                    z[j] = (p < L) ? pts[3 * p + 2] : 0.5f;
                }
            }

            float4* obase = reinterpret_cast<float4*>(out) + p0;
#pragma unroll
            for (int j = 0; j < 8; ++j) {
                const int p = p0 + j;
                if (p >= L) break;
                obase[j] = make_float4(x[j], y[j], z[j], 0.0f);

                int c = (cell_fast(z[j]) * GC + cell_fast(y[j])) * GC
                        + cell_fast(x[j]);
                unsigned int cn = s_cnt[c];              // LDS
                if (cn) {
                    int  lim = (cn == 255u) ? B : (int)cn;
                    bool all = (cn == 255u);
                    for (int k = 0; k < lim; ++k) {
                        int r = all ? k : (int)s_list[c * KCAP + k];
                        float dx = x[j] - srx[r];
                        float dy = y[j] - sry[r];
                        float dz = z[j] - srz[r];
                        float d2 = dx * dx + dy * dy + dz * dz;
                        unsigned long long key =
                            ~((((unsigned long long)__float_as_uint(d2)) << 32) |
                              (unsigned long long)(unsigned int)p);
                        // LDS guard block-coherent; smem atomic authoritative
                        if (key > s_best[r]) atomicMax(&s_best[r], key);
                    }
                }
            }
        }
    }
    __syncthreads();   // all smem atomics visible

    // ---- one global merge per block (<=128 atomics) ----
    if (tid < B) atomicMax(&g_best[tid], s_best[tid]);

    // ---- last-finishing block finalizes ----
    __threadfence();
    __syncthreads();
    __shared__ bool is_last;
    if (tid == 0) is_last = (atomicAdd(&g_done, 1u) == GRID - 1);
    __syncthreads();
    if (!is_last) return;

    // authoritative reads into s_best (reused as final keys) + reset
    if (tid < B) {
        s_best[tid] = atomicMax(&g_best[tid], 0ull);
        g_best[tid] = 0ull;                              // reset for next replay
    }
    __syncthreads();

    // ---- fallback: brute-force any receiver with sentinel idx (P~1.5e-4,
    //      never in practice; guarantees unconditional correctness) ----
    for (int r = 0; r < B; ++r) {
        unsigned int idx = ~((unsigned int)(s_best[r] & 0xffffffffull));
        if (idx != 0xFFFFFFFFu) continue;                // uniform (smem) branch
        float rx = srx[r], ry = sry[r], rz = srz[r];
        unsigned long long bb = 0ull;
        for (int p = tid; p < L; p += THREADS) {
            float dx = pts[3 * p + 0] - rx;
            float dy = pts[3 * p + 1] - ry;
            float dz = pts[3 * p + 2] - rz;
            float d2 = dx * dx + dy * dy + dz * dz;
            unsigned long long key =
                ~((((unsigned long long)__float_as_uint(d2)) << 32) |
                  (unsigned long long)(unsigned int)p);
            if (key > bb) bb = key;
        }
#pragma unroll
        for (int m = 16; m > 0; m >>= 1) {
            unsigned long long o = __shfl_xor_sync(0xffffffffu, bb, m);
            if (o > bb) bb = o;
        }
        if (lane == 0) s_red[wid] = bb;
        __syncthreads();
        if (tid == 0) {
            unsigned long long mb = s_red[0];
#pragma unroll
            for (int w = 1; w < THREADS / 32; ++w)
                if (s_red[w] > mb) mb = s_red[w];
            s_best[r] = mb;
        }
        __syncthreads();
    }

    // ---- write tail outputs ----
    if (tid < B) {
        unsigned int idx = ~((unsigned int)(s_best[tid] & 0xffffffffull));
        float* cp = out + 4 * (size_t)L;
        cp[3 * tid + 0] = pts[3 * idx + 0];
        cp[3 * tid + 1] = pts[3 * idx + 1];
        cp[3 * tid + 2] = pts[3 * idx + 2];
        out[4 * (size_t)L + 3 * B + tid] = (float)idx;   // min_index as float
        out[4 * (size_t)idx + 3] = 1.0f;                 // one-hot scatter
    }
    if (tid == 0) {
        if (B > 1) out[3] = 1.0f;        // reference quirk: index 0 also set
        g_done = 0u;                     // reset for next replay
    }
}

// ---------------------------------------------------------------------------
extern "C" void kernel_launch(void* const* d_in, const int* in_sizes, int n_in,
                              void* d_out, int out_size)
{
    const float* pts  = (const float*)d_in[0];   // mesh_3D flattened [L,3]
    const float* recv = (const float*)d_in[1];   // receiver_pos [B,3]
    float* out = (float*)d_out;

    int L = in_sizes[0] / 3;   // 1,000,000
    int B = in_sizes[1] / 3;   // 128

    fused_kernel<<<GRID, THREADS>>>(pts, recv, out, L, B);
}